// round 11
// baseline (speedup 1.0000x reference)
#include <cuda_runtime.h>

// AttentionStem: per-pixel 4x4 local window attention. B=4, IC=3, OC=64, H=W=128.
// R11 (= R10 resubmit after infra failure): hoist key projection
//      K[b][o][r][c] = k_o . x[:,r,c] into kproj_kernel (was recomputed 16x),
//      stored PRE-PAIRED (K[c],K[c+1]) so the attn mainloop replaces
//      24 fma2/channel with 8 aligned LDS.64 + 8 mul2. Dual accumulators.
//      8 channels/block, dynamic smem (~50.7KB), grid 2048.

typedef unsigned long long u64;

#define LOG2E 1.4426950408889634f

__device__ __forceinline__ u64 pk2(float lo, float hi) {
    u64 r; asm("mov.b64 %0,{%1,%2};" : "=l"(r) : "f"(lo), "f"(hi)); return r;
}
__device__ __forceinline__ void upk2(u64 a, float& lo, float& hi) {
    asm("mov.b64 {%0,%1},%2;" : "=f"(lo), "=f"(hi) : "l"(a));
}
__device__ __forceinline__ u64 fma2_(u64 a, u64 b, u64 c) {
    u64 r; asm("fma.rn.f32x2 %0,%1,%2,%3;" : "=l"(r) : "l"(a), "l"(b), "l"(c)); return r;
}
__device__ __forceinline__ u64 mul2_(u64 a, u64 b) {
    u64 r; asm("mul.rn.f32x2 %0,%1,%2;" : "=l"(r) : "l"(a), "l"(b)); return r;
}
__device__ __forceinline__ u64 add2_(u64 a, u64 b) {
    u64 r; asm("add.rn.f32x2 %0,%1,%2;" : "=l"(r) : "l"(a), "l"(b)); return r;
}
__device__ __forceinline__ float ex2_(float x) {
    float r; asm("ex2.approx.f32 %0,%1;" : "=f"(r) : "f"(x)); return r;
}
__device__ __forceinline__ float lo32(u64 a) {
    return __int_as_float((int)(unsigned)a);
}

// Precomputed key projection, pre-paired: g_K2[((b*64+o)*132 + r)*132 + c] =
// (K[r][c], K[r][c+1]) over the padded 132x132 image.
__device__ __align__(16) u64 g_K2[4 * 64 * 132 * 132];
// Mixed value weights (u64-packed pairs) and LOG2E-folded query weights.
__device__ u64    g_wv[64 * 24];   // [o][c][p], float view [o*48 + c*16 + ij]
__device__ float4 g_qw[64];

__global__ __launch_bounds__(256)
void kproj_kernel(const float* __restrict__ x, const float* __restrict__ key_w) {
    __shared__ float xrow[3][132];
    __shared__ float skw[192];
    __shared__ float sK[64][132];
    int t = threadIdx.x;
    int r = blockIdx.x % 132;
    int b = blockIdx.x / 132;

    for (int i = t; i < 396; i += 256) {
        int c3 = i / 132, c = i % 132;
        int hr = r - 2, wc = c - 2;
        float v = 0.f;
        if (hr >= 0 && hr < 128 && wc >= 0 && wc < 128)
            v = x[((b * 3 + c3) * 128 + hr) * 128 + wc];
        xrow[c3][c] = v;
    }
    if (t < 192) skw[t] = key_w[t];
    __syncthreads();

    for (int i = t; i < 8448; i += 256) {
        int o = i / 132, c = i % 132;
        sK[o][c] = skw[o * 3] * xrow[0][c] + skw[o * 3 + 1] * xrow[1][c]
                 + skw[o * 3 + 2] * xrow[2][c];
    }
    __syncthreads();

    for (int i = t; i < 8448; i += 256) {
        int o = i / 132, c = i % 132;
        float hi = (c < 131) ? sK[o][c + 1] : 0.f;
        g_K2[((size_t)((b * 64 + o) * 132 + r)) * 132 + c] = pk2(sK[o][c], hi);
    }
}

__global__ void prep_kernel(const float* __restrict__ query_w,
                            const float* __restrict__ value_w,
                            const float* __restrict__ emb_a,
                            const float* __restrict__ emb_b,
                            const float* __restrict__ emb_mix) {
    __shared__ float sh_lab[32];   // la: [i*4+m], lb: [16 + j*4+m]
    __shared__ float sh_emb[4][16];
    int t = threadIdx.x;

    {
        int outi = t >> 2;
        int chunk = t & 3;
        int m = outi & 3, i4 = (outi >> 2) & 3, ab = outi >> 4;
        const float* e = ab ? emb_b : emb_a;
        float s = 0.f;
#pragma unroll
        for (int oo = 0; oo < 16; oo++) {
            int o = chunk * 16 + oo;
            s += emb_mix[m * 64 + o] * e[o * 4 + i4];
        }
        s += __shfl_xor_sync(0xffffffffu, s, 1);
        s += __shfl_xor_sync(0xffffffffu, s, 2);
        if (chunk == 0) sh_lab[outi] = s;
    }
    __syncthreads();

    if (t < 16) {
        int i = t >> 2, j = t & 3;
        float lg[4];
#pragma unroll
        for (int m = 0; m < 4; m++)
            lg[m] = sh_lab[(i << 2) + m] + sh_lab[16 + (j << 2) + m];
        float mx = fmaxf(fmaxf(lg[0], lg[1]), fmaxf(lg[2], lg[3]));
        float e[4], s = 0.f;
#pragma unroll
        for (int m = 0; m < 4; m++) { e[m] = __expf(lg[m] - mx); s += e[m]; }
        float inv = __fdividef(1.f, s);
#pragma unroll
        for (int m = 0; m < 4; m++) sh_emb[m][t] = e[m] * inv;
    }
    __syncthreads();

    float* wvf = (float*)g_wv;
    for (int f = t; f < 3072; f += 128) {
        int o = f / 48, r = f % 48, c = r >> 4, ij = r & 15;
        float acc = 0.f;
#pragma unroll
        for (int m = 0; m < 4; m++)
            acc += sh_emb[m][ij] * value_w[(m * 64 + o) * 3 + c];
        wvf[f] = acc;
    }
    if (t < 64) {
        g_qw[t] = make_float4(query_w[t * 3] * LOG2E,
                              query_w[t * 3 + 1] * LOG2E,
                              query_w[t * 3 + 2] * LOG2E, 0.f);
    }
}

// Dynamic smem layout (bytes):
//   [0, 42240)            sh_K2 : 8ch x 5 rows x 132 pair-cols (u64)
//   [42240, 50160)        sh_x  : 3ch x 5 rows x 132 cols (float)
//   [50160, 51696)        sh_wv : 8ch x 24 (u64)
//   [51696, 51824)        sh_qw : 8 float4
#define SMEM_BYTES 51824

__global__ __launch_bounds__(256)
void attn_kernel(const float* __restrict__ x, float* __restrict__ out) {
    extern __shared__ char dynsm[];
    u64*    sh_K2 = (u64*)dynsm;
    float*  sh_x  = (float*)(dynsm + 42240);
    u64*    sh_wv = (u64*)(dynsm + 50160);
    float4* sh_qw = (float4*)(dynsm + 51696);

    int tid = threadIdx.x;
    int oq = blockIdx.x & 7;             // eighth of the 64 channels
    int rest = blockIdx.x >> 3;
    int b = rest >> 6;
    int h0 = (rest & 63) * 2;            // output rows h0, h0+1

    // Prologue (copy-only): x tile, K2 tile, wv, qw; one barrier.
    for (int idx = tid; idx < 1980; idx += 256) {
        int c = idx / 660, rem = idx % 660, rr = rem / 132, cc = rem % 132;
        int hr = h0 - 2 + rr, wc = cc - 2;
        float v = 0.f;
        if (hr >= 0 && hr < 128 && wc >= 0 && wc < 128)
            v = x[((b * 3 + c) * 128 + hr) * 128 + wc];
        sh_x[idx] = v;
    }
    // K2 tile: 8 channels x 5 rows x 132 pairs = 2640 ulonglong2.
    {
        ulonglong2* dst = (ulonglong2*)sh_K2;
        for (int idx = tid; idx < 2640; idx += 256) {
            int o = idx / 330, rem = idx % 330, rr = rem / 66, c2 = rem % 66;
            const ulonglong2* src = (const ulonglong2*)(
                g_K2 + ((size_t)((b * 64 + oq * 8 + o) * 132 + h0 + rr)) * 132 + c2 * 2);
            dst[idx] = *src;
        }
    }
    if (tid < 96) {
        const ulonglong2* src = (const ulonglong2*)(g_wv + oq * 192);
        ((ulonglong2*)sh_wv)[tid] = src[tid];
    }
    if (tid >= 96 && tid < 104) {
        sh_qw[tid - 96] = g_qw[oq * 8 + (tid - 96)];
    }
    __syncthreads();

    int r0 = tid >> 7;                   // row within the pair (warp-uniform)
    int w = tid & 127;

    // Window into registers for q + value dots.
    u64 wp0[8], wp1[8], wp2[8];
#pragma unroll
    for (int p = 0; p < 8; p++) {
        int i = (p >> 1) + r0, j0 = (p & 1) * 2;
        wp0[p] = pk2(sh_x[0 * 660 + i * 132 + w + j0], sh_x[0 * 660 + i * 132 + w + j0 + 1]);
        wp1[p] = pk2(sh_x[1 * 660 + i * 132 + w + j0], sh_x[1 * 660 + i * 132 + w + j0 + 1]);
        wp2[p] = pk2(sh_x[2 * 660 + i * 132 + w + j0], sh_x[2 * 660 + i * 132 + w + j0 + 1]);
    }

    const u64* kbase = sh_K2 + r0 * 132 + w;
    float* outp = out + (((b * 64) + oq * 8) * 128 + (h0 + r0)) * 128 + w;

#pragma unroll 2
    for (int o = 0; o < 8; o++) {
        float4 qw = sh_qw[o];
        // center pixel = low half of pair 5 (i=2, j=2); LOG2E folded into qw
        float q = qw.x * lo32(wp0[5]) + qw.y * lo32(wp1[5]) + qw.z * lo32(wp2[5]);
        u64 qq = pk2(q, q);
        const u64* kxp = kbase + o * 660;
        const u64* wvp = sh_wv + o * 24;

        u64 accA = 0ull, ssA = 0ull, accB = 0ull, ssB = 0ull;
#pragma unroll
        for (int pp = 0; pp < 4; pp++) {
            ulonglong2 wv0 = *(const ulonglong2*)(wvp + 2 * pp);
            ulonglong2 wv1 = *(const ulonglong2*)(wvp + 8 + 2 * pp);
            ulonglong2 wv2 = *(const ulonglong2*)(wvp + 16 + 2 * pp);
            {
                int p = 2 * pp;                    // even pair -> chain A
                u64 kx = kxp[(p >> 1) * 132 + (p & 1) * 2];
                u64 l2 = mul2_(qq, kx);
                float l0, l1; upk2(l2, l0, l1);
                u64 e2 = pk2(ex2_(l0), ex2_(l1));
                u64 v2 = fma2_(wv0.x, wp0[p], fma2_(wv1.x, wp1[p], mul2_(wv2.x, wp2[p])));
                accA = fma2_(e2, v2, accA);
                ssA  = add2_(e2, ssA);
            }
            {
                int p = 2 * pp + 1;                // odd pair -> chain B
                u64 kx = kxp[(p >> 1) * 132 + (p & 1) * 2];
                u64 l2 = mul2_(qq, kx);
                float l0, l1; upk2(l2, l0, l1);
                u64 e2 = pk2(ex2_(l0), ex2_(l1));
                u64 v2 = fma2_(wv0.y, wp0[p], fma2_(wv1.y, wp1[p], mul2_(wv2.y, wp2[p])));
                accB = fma2_(e2, v2, accB);
                ssB  = add2_(e2, ssB);
            }
        }
        u64 acc = add2_(accA, accB);
        u64 ss  = add2_(ssA, ssB);
        float a0, a1, s0, s1;
        upk2(acc, a0, a1);
        upk2(ss, s0, s1);
        outp[o * 16384] = __fdividef(a0 + a1, s0 + s1);
    }
}

extern "C" void kernel_launch(void* const* d_in, const int* in_sizes, int n_in,
                              void* d_out, int out_size) {
    const float* x       = (const float*)d_in[0];
    const float* key_w   = (const float*)d_in[1];
    const float* query_w = (const float*)d_in[2];
    const float* value_w = (const float*)d_in[3];
    const float* emb_a   = (const float*)d_in[4];
    const float* emb_b   = (const float*)d_in[5];
    const float* emb_mix = (const float*)d_in[6];
    float* out = (float*)d_out;

    cudaFuncSetAttribute(attn_kernel, cudaFuncAttributeMaxDynamicSharedMemorySize,
                         SMEM_BYTES);
    prep_kernel<<<1, 128>>>(query_w, value_w, emb_a, emb_b, emb_mix);
    kproj_kernel<<<528, 256>>>(x, key_w);
    attn_kernel<<<2048, 256, SMEM_BYTES>>>(x, out);
}

// round 12
// speedup vs baseline: 1.7736x; 1.7736x over previous
#include <cuda_runtime.h>

// AttentionStem: per-pixel 4x4 local window attention. B=4, IC=3, OC=64, H=W=128.
// R12: revert to R6 winner (K2 hoist was a 72us disaster); two fixes:
//  (a) prep: one-DRAM-round bulk load to shared + warp-parallel dots
//      (was ~6 serial DRAM round-trips, 10.4us standalone);
//  (b) attn mainloop: dual accumulator chains (halve acc dep chain),
//      launch_bounds(256,3) to guard the 3-CTA/SM residency cliff.

typedef unsigned long long u64;

#define LOG2E 1.4426950408889634f

__device__ __forceinline__ u64 pk2(float lo, float hi) {
    u64 r; asm("mov.b64 %0,{%1,%2};" : "=l"(r) : "f"(lo), "f"(hi)); return r;
}
__device__ __forceinline__ void upk2(u64 a, float& lo, float& hi) {
    asm("mov.b64 {%0,%1},%2;" : "=f"(lo), "=f"(hi) : "l"(a));
}
__device__ __forceinline__ u64 fma2_(u64 a, u64 b, u64 c) {
    u64 r; asm("fma.rn.f32x2 %0,%1,%2,%3;" : "=l"(r) : "l"(a), "l"(b), "l"(c)); return r;
}
__device__ __forceinline__ u64 mul2_(u64 a, u64 b) {
    u64 r; asm("mul.rn.f32x2 %0,%1,%2;" : "=l"(r) : "l"(a), "l"(b)); return r;
}
__device__ __forceinline__ u64 add2_(u64 a, u64 b) {
    u64 r; asm("add.rn.f32x2 %0,%1,%2;" : "=l"(r) : "l"(a), "l"(b)); return r;
}
__device__ __forceinline__ float ex2_(float x) {
    float r; asm("ex2.approx.f32 %0,%1;" : "=f"(r) : "f"(x)); return r;
}
__device__ __forceinline__ float lo32(u64 a) {
    return __int_as_float((int)(unsigned)a);
}

// Precomputed: mixed value weights (u64-packed pairs) and folded q/k weights.
__device__ u64    g_wv[64 * 24];   // [o][c][p], float view [o*48 + c*16 + ij]
__device__ float4 g_kw[64];
__device__ float4 g_qw[64];        // pre-scaled by LOG2E

__global__ __launch_bounds__(256)
void prep_kernel(const float* __restrict__ key_w,
                 const float* __restrict__ query_w,
                 const float* __restrict__ value_w,
                 const float* __restrict__ emb_a,
                 const float* __restrict__ emb_b,
                 const float* __restrict__ emb_mix) {
    // Shared input staging (all global loads issued before the first barrier).
    __shared__ float sh_vw[768];    // value_w [m][o][c]
    __shared__ float sh_mix[256];   // emb_mix [m][o]
    __shared__ float sh_ab[512];    // emb_a [o][i] at 0, emb_b [o][j] at 256
    __shared__ float sh_lab[32];    // la: [i*4+m], lb: [16 + j*4+m]
    __shared__ float sh_emb[4][16];
    int t = threadIdx.x;

    // Stage 0: bulk load via float4; each thread <=2 independent loads.
    if (t < 192) {
        ((float4*)sh_vw)[t] = ((const float4*)value_w)[t];
    } else {
        ((float4*)sh_mix)[t - 192] = ((const float4*)emb_mix)[t - 192];
    }
    if (t < 64) {
        ((float4*)sh_ab)[t] = ((const float4*)emb_a)[t];
    } else if (t < 128) {
        ((float4*)sh_ab)[t] = ((const float4*)emb_b)[t - 64];
    } else if (t < 192) {
        // kw/qw: independent of emb; write straight to globals.
        int o = t - 128;
        g_kw[o] = make_float4(key_w[o * 3], key_w[o * 3 + 1], key_w[o * 3 + 2], 0.f);
        g_qw[o] = make_float4(query_w[o * 3] * LOG2E,
                              query_w[o * 3 + 1] * LOG2E,
                              query_w[o * 3 + 2] * LOG2E, 0.f);
    }
    __syncthreads();

    // Stage 1: 32 dots of length 64 (la/lb), 8 threads per dot, shfl-reduced.
    {
        int d = t >> 3;                    // 0..31: ab*16 + i4*4 + m
        int part = t & 7;
        int m = d & 3, i4 = (d >> 2) & 3, ab = d >> 4;
        const float* e = sh_ab + ab * 256;
        float s = 0.f;
#pragma unroll
        for (int k = 0; k < 8; k++) {
            int o = part * 8 + k;
            s += sh_mix[m * 64 + o] * e[o * 4 + i4];
        }
        s += __shfl_xor_sync(0xffffffffu, s, 1);
        s += __shfl_xor_sync(0xffffffffu, s, 2);
        s += __shfl_xor_sync(0xffffffffu, s, 4);
        if (part == 0) sh_lab[d] = s;
    }
    __syncthreads();

    // Stage 2: softmax over m per window position.
    if (t < 16) {
        int i = t >> 2, j = t & 3;
        float lg[4];
#pragma unroll
        for (int m = 0; m < 4; m++)
            lg[m] = sh_lab[(i << 2) + m] + sh_lab[16 + (j << 2) + m];
        float mx = fmaxf(fmaxf(lg[0], lg[1]), fmaxf(lg[2], lg[3]));
        float e[4], s = 0.f;
#pragma unroll
        for (int m = 0; m < 4; m++) { e[m] = __expf(lg[m] - mx); s += e[m]; }
        float inv = __fdividef(1.f, s);
#pragma unroll
        for (int m = 0; m < 4; m++) sh_emb[m][t] = e[m] * inv;
    }
    __syncthreads();

    // Stage 3: mixed value weights (3072 floats), all from shared.
    float* wvf = (float*)g_wv;
#pragma unroll
    for (int k = 0; k < 12; k++) {
        int f = t + k * 256;
        int o = f / 48, r = f % 48, c = r >> 4, ij = r & 15;
        float acc = 0.f;
#pragma unroll
        for (int m = 0; m < 4; m++)
            acc += sh_emb[m][ij] * sh_vw[(m * 64 + o) * 3 + c];
        wvf[f] = acc;
    }
}

__global__ __launch_bounds__(256, 3)
void attn_kernel(const float* __restrict__ x, float* __restrict__ out) {
    __shared__ float  sh_x[3][5][132];   // [c][tile row][padded col]
    __shared__ float4 sh_kw[16];
    __shared__ float4 sh_qw[16];
    __shared__ u64    sh_wv[16 * 24];    // [o][c][p]

    int tid = threadIdx.x;
    int oq = blockIdx.x & 3;             // quarter of the 64 channels
    int rest = blockIdx.x >> 2;
    int b = rest >> 6;
    int h0 = (rest & 63) * 2;            // output rows h0, h0+1

    // Copy-only prologue: 5-row x tile + wv slice + kw/qw slice; single barrier.
    for (int idx = tid; idx < 3 * 5 * 132; idx += 256) {
        int c = idx / 660, rem = idx % 660, r = rem / 132, cc = rem % 132;
        int hr = h0 - 2 + r, wc = cc - 2;
        float v = 0.f;
        if (hr >= 0 && hr < 128 && wc >= 0 && wc < 128)
            v = x[((b * 3 + c) * 128 + hr) * 128 + wc];
        sh_x[c][r][cc] = v;
    }
    // wv slice: 384 u64 = 192 ulonglong2 over 256 threads.
    if (tid < 192) {
        const ulonglong2* src = (const ulonglong2*)(g_wv + oq * 384);
        ((ulonglong2*)sh_wv)[tid] = src[tid];
    }
    if (tid >= 192 && tid < 208) {
        sh_kw[tid - 192] = g_kw[oq * 16 + (tid - 192)];
        sh_qw[tid - 192] = g_qw[oq * 16 + (tid - 192)];
    }
    __syncthreads();

    // This thread's pixel: row group r0 (0/1), column w.
    int r0 = tid >> 7;
    int w = tid & 127;

    // Window into registers, packed by (same i, adjacent j) pairs.
    u64 wp0[8], wp1[8], wp2[8];
#pragma unroll
    for (int p = 0; p < 8; p++) {
        int i = (p >> 1) + r0, j0 = (p & 1) * 2;
        wp0[p] = pk2(sh_x[0][i][w + j0], sh_x[0][i][w + j0 + 1]);
        wp1[p] = pk2(sh_x[1][i][w + j0], sh_x[1][i][w + j0 + 1]);
        wp2[p] = pk2(sh_x[2][i][w + j0], sh_x[2][i][w + j0 + 1]);
    }

    float* outp = out + (((b * 64) + oq * 16) * 128 + (h0 + r0)) * 128 + w;

#pragma unroll 2
    for (int o = 0; o < 16; o++) {
        float4 qw = sh_qw[o];
        // center pixel = low half of pair 5 (i=2, j=2)
        float q = qw.x * lo32(wp0[5]) + qw.y * lo32(wp1[5]) + qw.z * lo32(wp2[5]);
        float4 kw = sh_kw[o];
        float qk0 = q * kw.x, qk1 = q * kw.y, qk2 = q * kw.z;
        u64 k0 = pk2(qk0, qk0), k1 = pk2(qk1, qk1), k2 = pk2(qk2, qk2);
        const u64* wvp = sh_wv + o * 24;

        u64 accA = 0ull, ssA = 0ull, accB = 0ull, ssB = 0ull;
#pragma unroll
        for (int pp = 0; pp < 4; pp++) {
            ulonglong2 wv0 = *(const ulonglong2*)(wvp + 2 * pp);
            ulonglong2 wv1 = *(const ulonglong2*)(wvp + 8 + 2 * pp);
            ulonglong2 wv2 = *(const ulonglong2*)(wvp + 16 + 2 * pp);
            {
                int p = 2 * pp;                    // even pair -> chain A
                u64 l2 = fma2_(k0, wp0[p], fma2_(k1, wp1[p], mul2_(k2, wp2[p])));
                float l0, l1; upk2(l2, l0, l1);
                u64 e2 = pk2(ex2_(l0), ex2_(l1));
                u64 v2 = fma2_(wv0.x, wp0[p], fma2_(wv1.x, wp1[p], mul2_(wv2.x, wp2[p])));
                accA = fma2_(e2, v2, accA);
                ssA  = add2_(e2, ssA);
            }
            {
                int p = 2 * pp + 1;                // odd pair -> chain B
                u64 l2 = fma2_(k0, wp0[p], fma2_(k1, wp1[p], mul2_(k2, wp2[p])));
                float l0, l1; upk2(l2, l0, l1);
                u64 e2 = pk2(ex2_(l0), ex2_(l1));
                u64 v2 = fma2_(wv0.y, wp0[p], fma2_(wv1.y, wp1[p], mul2_(wv2.y, wp2[p])));
                accB = fma2_(e2, v2, accB);
                ssB  = add2_(e2, ssB);
            }
        }
        u64 acc = add2_(accA, accB);
        u64 ss  = add2_(ssA, ssB);
        float a0, a1, s0, s1;
        upk2(acc, a0, a1);
        upk2(ss, s0, s1);
        outp[o * 16384] = __fdividef(a0 + a1, s0 + s1);
    }
}

extern "C" void kernel_launch(void* const* d_in, const int* in_sizes, int n_in,
                              void* d_out, int out_size) {
    const float* x       = (const float*)d_in[0];
    const float* key_w   = (const float*)d_in[1];
    const float* query_w = (const float*)d_in[2];
    const float* value_w = (const float*)d_in[3];
    const float* emb_a   = (const float*)d_in[4];
    const float* emb_b   = (const float*)d_in[5];
    const float* emb_mix = (const float*)d_in[6];
    float* out = (float*)d_out;

    prep_kernel<<<1, 256>>>(key_w, query_w, value_w, emb_a, emb_b, emb_mix);
    attn_kernel<<<1024, 256>>>(x, out);
}

// round 13
// speedup vs baseline: 1.8356x; 1.0350x over previous
#include <cuda_runtime.h>

// AttentionStem: per-pixel 4x4 local window attention. B=4, IC=3, OC=64, H=W=128.
// R13: consolidation of measured-best pieces:
//  - attn mainloop = R6 exactly (single acc chain; 36.6us measured; dual-chain
//    variant R12 was 38.9us -> reverted),
//  - prep = R12 (one DRAM round, warp-parallel dots; ~1.8us total overhead),
//  - launch_bounds(256,3) kept only as a residency-cliff guard.

typedef unsigned long long u64;

#define LOG2E 1.4426950408889634f

__device__ __forceinline__ u64 pk2(float lo, float hi) {
    u64 r; asm("mov.b64 %0,{%1,%2};" : "=l"(r) : "f"(lo), "f"(hi)); return r;
}
__device__ __forceinline__ void upk2(u64 a, float& lo, float& hi) {
    asm("mov.b64 {%0,%1},%2;" : "=f"(lo), "=f"(hi) : "l"(a));
}
__device__ __forceinline__ u64 fma2_(u64 a, u64 b, u64 c) {
    u64 r; asm("fma.rn.f32x2 %0,%1,%2,%3;" : "=l"(r) : "l"(a), "l"(b), "l"(c)); return r;
}
__device__ __forceinline__ u64 mul2_(u64 a, u64 b) {
    u64 r; asm("mul.rn.f32x2 %0,%1,%2;" : "=l"(r) : "l"(a), "l"(b)); return r;
}
__device__ __forceinline__ u64 add2_(u64 a, u64 b) {
    u64 r; asm("add.rn.f32x2 %0,%1,%2;" : "=l"(r) : "l"(a), "l"(b)); return r;
}
__device__ __forceinline__ float ex2_(float x) {
    float r; asm("ex2.approx.f32 %0,%1;" : "=f"(r) : "f"(x)); return r;
}
__device__ __forceinline__ float lo32(u64 a) {
    return __int_as_float((int)(unsigned)a);
}

// Precomputed: mixed value weights (u64-packed pairs) and folded q/k weights.
__device__ u64    g_wv[64 * 24];   // [o][c][p], float view [o*48 + c*16 + ij]
__device__ float4 g_kw[64];
__device__ float4 g_qw[64];        // pre-scaled by LOG2E

__global__ __launch_bounds__(256)
void prep_kernel(const float* __restrict__ key_w,
                 const float* __restrict__ query_w,
                 const float* __restrict__ value_w,
                 const float* __restrict__ emb_a,
                 const float* __restrict__ emb_b,
                 const float* __restrict__ emb_mix) {
    // Shared input staging (all global loads issued before the first barrier).
    __shared__ float sh_vw[768];    // value_w [m][o][c]
    __shared__ float sh_mix[256];   // emb_mix [m][o]
    __shared__ float sh_ab[512];    // emb_a [o][i] at 0, emb_b [o][j] at 256
    __shared__ float sh_lab[32];    // la: [i*4+m], lb: [16 + j*4+m]
    __shared__ float sh_emb[4][16];
    int t = threadIdx.x;

    // Stage 0: bulk load via float4; each thread <=2 independent loads.
    if (t < 192) {
        ((float4*)sh_vw)[t] = ((const float4*)value_w)[t];
    } else {
        ((float4*)sh_mix)[t - 192] = ((const float4*)emb_mix)[t - 192];
    }
    if (t < 64) {
        ((float4*)sh_ab)[t] = ((const float4*)emb_a)[t];
    } else if (t < 128) {
        ((float4*)sh_ab)[t] = ((const float4*)emb_b)[t - 64];
    } else if (t < 192) {
        // kw/qw: independent of emb; write straight to globals.
        int o = t - 128;
        g_kw[o] = make_float4(key_w[o * 3], key_w[o * 3 + 1], key_w[o * 3 + 2], 0.f);
        g_qw[o] = make_float4(query_w[o * 3] * LOG2E,
                              query_w[o * 3 + 1] * LOG2E,
                              query_w[o * 3 + 2] * LOG2E, 0.f);
    }
    __syncthreads();

    // Stage 1: 32 dots of length 64 (la/lb), 8 threads per dot, shfl-reduced.
    {
        int d = t >> 3;                    // 0..31: ab*16 + i4*4 + m
        int part = t & 7;
        int m = d & 3, i4 = (d >> 2) & 3, ab = d >> 4;
        const float* e = sh_ab + ab * 256;
        float s = 0.f;
#pragma unroll
        for (int k = 0; k < 8; k++) {
            int o = part * 8 + k;
            s += sh_mix[m * 64 + o] * e[o * 4 + i4];
        }
        s += __shfl_xor_sync(0xffffffffu, s, 1);
        s += __shfl_xor_sync(0xffffffffu, s, 2);
        s += __shfl_xor_sync(0xffffffffu, s, 4);
        if (part == 0) sh_lab[d] = s;
    }
    __syncthreads();

    // Stage 2: softmax over m per window position.
    if (t < 16) {
        int i = t >> 2, j = t & 3;
        float lg[4];
#pragma unroll
        for (int m = 0; m < 4; m++)
            lg[m] = sh_lab[(i << 2) + m] + sh_lab[16 + (j << 2) + m];
        float mx = fmaxf(fmaxf(lg[0], lg[1]), fmaxf(lg[2], lg[3]));
        float e[4], s = 0.f;
#pragma unroll
        for (int m = 0; m < 4; m++) { e[m] = __expf(lg[m] - mx); s += e[m]; }
        float inv = __fdividef(1.f, s);
#pragma unroll
        for (int m = 0; m < 4; m++) sh_emb[m][t] = e[m] * inv;
    }
    __syncthreads();

    // Stage 3: mixed value weights (3072 floats), all from shared.
    float* wvf = (float*)g_wv;
#pragma unroll
    for (int k = 0; k < 12; k++) {
        int f = t + k * 256;
        int o = f / 48, r = f % 48, c = r >> 4, ij = r & 15;
        float acc = 0.f;
#pragma unroll
        for (int m = 0; m < 4; m++)
            acc += sh_emb[m][ij] * sh_vw[(m * 64 + o) * 3 + c];
        wvf[f] = acc;
    }
}

__global__ __launch_bounds__(256, 3)
void attn_kernel(const float* __restrict__ x, float* __restrict__ out) {
    __shared__ float  sh_x[3][5][132];   // [c][tile row][padded col]
    __shared__ float4 sh_kw[16];
    __shared__ float4 sh_qw[16];
    __shared__ u64    sh_wv[16 * 24];    // [o][c][p]

    int tid = threadIdx.x;
    int oq = blockIdx.x & 3;             // quarter of the 64 channels
    int rest = blockIdx.x >> 2;
    int b = rest >> 6;
    int h0 = (rest & 63) * 2;            // output rows h0, h0+1

    // Copy-only prologue: 5-row x tile + wv slice + kw/qw slice; single barrier.
    for (int idx = tid; idx < 3 * 5 * 132; idx += 256) {
        int c = idx / 660, rem = idx % 660, r = rem / 132, cc = rem % 132;
        int hr = h0 - 2 + r, wc = cc - 2;
        float v = 0.f;
        if (hr >= 0 && hr < 128 && wc >= 0 && wc < 128)
            v = x[((b * 3 + c) * 128 + hr) * 128 + wc];
        sh_x[c][r][cc] = v;
    }
    // wv slice: 384 u64 = 192 ulonglong2 over 256 threads.
    if (tid < 192) {
        const ulonglong2* src = (const ulonglong2*)(g_wv + oq * 384);
        ((ulonglong2*)sh_wv)[tid] = src[tid];
    }
    if (tid >= 192 && tid < 208) {
        sh_kw[tid - 192] = g_kw[oq * 16 + (tid - 192)];
        sh_qw[tid - 192] = g_qw[oq * 16 + (tid - 192)];
    }
    __syncthreads();

    // This thread's pixel: row group r0 (0/1), column w.
    int r0 = tid >> 7;
    int w = tid & 127;

    // Window into registers, packed by (same i, adjacent j) pairs.
    u64 wp0[8], wp1[8], wp2[8];
#pragma unroll
    for (int p = 0; p < 8; p++) {
        int i = (p >> 1) + r0, j0 = (p & 1) * 2;
        wp0[p] = pk2(sh_x[0][i][w + j0], sh_x[0][i][w + j0 + 1]);
        wp1[p] = pk2(sh_x[1][i][w + j0], sh_x[1][i][w + j0 + 1]);
        wp2[p] = pk2(sh_x[2][i][w + j0], sh_x[2][i][w + j0 + 1]);
    }

    float* outp = out + (((b * 64) + oq * 16) * 128 + (h0 + r0)) * 128 + w;

#pragma unroll 2
    for (int o = 0; o < 16; o++) {
        float4 qw = sh_qw[o];
        // center pixel = low half of pair 5 (i=2, j=2)
        float q = qw.x * lo32(wp0[5]) + qw.y * lo32(wp1[5]) + qw.z * lo32(wp2[5]);
        float4 kw = sh_kw[o];
        float qk0 = q * kw.x, qk1 = q * kw.y, qk2 = q * kw.z;
        u64 k0 = pk2(qk0, qk0), k1 = pk2(qk1, qk1), k2 = pk2(qk2, qk2);
        const u64* wvp = sh_wv + o * 24;

        u64 acc = 0ull, ss = 0ull;
#pragma unroll
        for (int pp = 0; pp < 4; pp++) {
            ulonglong2 wv0 = *(const ulonglong2*)(wvp + 2 * pp);
            ulonglong2 wv1 = *(const ulonglong2*)(wvp + 8 + 2 * pp);
            ulonglong2 wv2 = *(const ulonglong2*)(wvp + 16 + 2 * pp);
            {
                int p = 2 * pp;
                u64 l2 = fma2_(k0, wp0[p], fma2_(k1, wp1[p], mul2_(k2, wp2[p])));
                float l0, l1; upk2(l2, l0, l1);
                u64 e2 = pk2(ex2_(l0), ex2_(l1));
                u64 v2 = fma2_(wv0.x, wp0[p], fma2_(wv1.x, wp1[p], mul2_(wv2.x, wp2[p])));
                acc = fma2_(e2, v2, acc);
                ss  = add2_(e2, ss);
            }
            {
                int p = 2 * pp + 1;
                u64 l2 = fma2_(k0, wp0[p], fma2_(k1, wp1[p], mul2_(k2, wp2[p])));
                float l0, l1; upk2(l2, l0, l1);
                u64 e2 = pk2(ex2_(l0), ex2_(l1));
                u64 v2 = fma2_(wv0.y, wp0[p], fma2_(wv1.y, wp1[p], mul2_(wv2.y, wp2[p])));
                acc = fma2_(e2, v2, acc);
                ss  = add2_(e2, ss);
            }
        }
        float a0, a1, s0, s1;
        upk2(acc, a0, a1);
        upk2(ss, s0, s1);
        outp[o * 16384] = __fdividef(a0 + a1, s0 + s1);
    }
}

extern "C" void kernel_launch(void* const* d_in, const int* in_sizes, int n_in,
                              void* d_out, int out_size) {
    const float* x       = (const float*)d_in[0];
    const float* key_w   = (const float*)d_in[1];
    const float* query_w = (const float*)d_in[2];
    const float* value_w = (const float*)d_in[3];
    const float* emb_a   = (const float*)d_in[4];
    const float* emb_b   = (const float*)d_in[5];
    const float* emb_mix = (const float*)d_in[6];
    float* out = (float*)d_out;

    prep_kernel<<<1, 256>>>(key_w, query_w, value_w, emb_a, emb_b, emb_mix);
    attn_kernel<<<1024, 256>>>(x, out);
}